// round 14
// baseline (speedup 1.0000x reference)
#include <cuda_runtime.h>
#include <cuda_fp16.h>
#include <cstdint>

// Problem constants
#define N_ 32
#define D_ 128
#define S_ 128
#define M_ 64
#define MM_ (M_*M_)

// ---------------- scratch (__device__ globals; no allocations allowed) ----------------
__device__ uint32_t g_xh[N_*64*4096];   // x as fp16 k-pair packed: [n][dp=d/2][ij]
__device__ uint4    g_cfrag[2048];      // c2 fp16 in m16n8k16 A-fragment order
__device__ float    g_mcdg[N_*D_*M_*2]; // interleaved (mc, dg)
__device__ float    g_md[N_*D_];
__device__ float    g_ma[N_*D_];
__device__ float    g_c13[D_*S_*2];
__device__ float    g_c45[D_*S_*2];
__device__ float    g_P[N_*S_*M_];
__device__ float    g_Q[N_*S_];

__device__ __forceinline__ uint32_t packh2(float lo, float hi) {
    __half2 h = __halves2half2(__float2half_rn(lo), __float2half_rn(hi));
    return *reinterpret_cast<uint32_t*>(&h);
}
__device__ __forceinline__ void cp16(void* s, const void* g) {
    uint32_t sa = (uint32_t)__cvta_generic_to_shared(s);
    asm volatile("cp.async.cg.shared.global [%0], [%1], 16;\n" :: "r"(sa), "l"(g));
}
#define CP_COMMIT() asm volatile("cp.async.commit_group;\n" ::: "memory")
#define CP_WAIT(Nn) asm volatile("cp.async.wait_group %0;\n" :: "n"(Nn) : "memory")

// ---------------- kernel 0: coeff prep ----------------
__global__ __launch_bounds__(256) void prep_kernel(const float* __restrict__ coeffs) {
    int b = blockIdx.x, t = threadIdx.x;
    if (b < 64) {
        int idx = b * 256 + t;                 // d*S + s
        const float* c = coeffs + idx * 5;
        g_c13[idx*2]     = 0.5f * c[0];
        g_c13[idx*2 + 1] = 0.5f * c[2];
        g_c45[idx*2]     = c[3];
        g_c45[idx*2 + 1] = c[4];
    } else {
        int fid  = (b - 64) * 256 + t;         // 0..2047
        int mt   = fid & 1;
        int lane = (fid >> 1) & 31;
        int wr   = (fid >> 6) & 3;
        int kc   = fid >> 8;
        int g    = lane >> 2, tig = lane & 3;
        int srow = wr * 32 + mt * 16 + g;
        int k0   = kc * 16;
        #define C2V(d, s) coeffs[(((d) * S_) + (s)) * 5 + 1]
        uint4 v;
        v.x = packh2(C2V(k0 + 2*tig,     srow    ), C2V(k0 + 2*tig + 1,     srow    ));
        v.y = packh2(C2V(k0 + 2*tig,     srow + 8), C2V(k0 + 2*tig + 1,     srow + 8));
        v.z = packh2(C2V(k0 + 8 + 2*tig, srow    ), C2V(k0 + 8 + 2*tig + 1, srow    ));
        v.w = packh2(C2V(k0 + 8 + 2*tig, srow + 8), C2V(k0 + 8 + 2*tig + 1, srow + 8));
        #undef C2V
        g_cfrag[fid] = v;
    }
}

// ---------------- kernel 1: stats + fp16 pack ----------------
__global__ __launch_bounds__(256) void stats_kernel(const float* __restrict__ x) {
    int blk = blockIdx.x;
    int n   = blk >> 6;
    int dp  = blk & 63;
    const float* p0 = x + ((size_t)(n * D_ + 2*dp)) * MM_;
    const float* p1 = p0 + MM_;
    uint32_t* xo = g_xh + ((size_t)(n * 64 + dp)) * 4096;

    int t = threadIdx.x;
    int q = t & 15, r = t >> 4;

    float4 s0 = make_float4(0,0,0,0), s1 = make_float4(0,0,0,0);
    #pragma unroll
    for (int k = 0; k < 4; k++) {
        int off = (k*16 + r) * M_ + q * 4;
        float4 v0 = *(const float4*)(p0 + off);
        float4 v1 = *(const float4*)(p1 + off);
        s0.x += v0.x; s0.y += v0.y; s0.z += v0.z; s0.w += v0.w;
        s1.x += v1.x; s1.y += v1.y; s1.z += v1.z; s1.w += v1.w;
        uint4 pk;
        pk.x = packh2(v0.x, v1.x);
        pk.y = packh2(v0.y, v1.y);
        pk.z = packh2(v0.z, v1.z);
        pk.w = packh2(v0.w, v1.w);
        *(uint4*)(xo + off) = pk;
    }

    __shared__ float4 part0[256], part1[256];
    __shared__ float  diags0[64], diags1[64];
    __shared__ float  red0[16], red1[16], redd0[16], redd1[16];
    part0[t] = s0; part1[t] = s1;
    if (t < M_) { diags0[t] = p0[t * 65]; diags1[t] = p1[t * 65]; }
    __syncthreads();

    if (t < 16) {
        float4 c0 = part0[t], c1 = part1[t];
        #pragma unroll
        for (int rr = 1; rr < 16; rr++) {
            float4 a = part0[rr*16 + t], b = part1[rr*16 + t];
            c0.x += a.x; c0.y += a.y; c0.z += a.z; c0.w += a.w;
            c1.x += b.x; c1.y += b.y; c1.z += b.z; c1.w += b.w;
        }
        float m0[4] = { c0.x*(1.f/M_), c0.y*(1.f/M_), c0.z*(1.f/M_), c0.w*(1.f/M_) };
        float m1[4] = { c1.x*(1.f/M_), c1.y*(1.f/M_), c1.z*(1.f/M_), c1.w*(1.f/M_) };
        float2* o0 = ((float2*)g_mcdg) + (n*D_ + 2*dp    ) * M_ + t*4;
        float2* o1 = ((float2*)g_mcdg) + (n*D_ + 2*dp + 1) * M_ + t*4;
        #pragma unroll
        for (int c = 0; c < 4; c++) {
            int v = t*4 + c;
            float2 a; a.x = m0[c]; a.y = diags0[v]; o0[c] = a;
            float2 bb; bb.x = m1[c]; bb.y = diags1[v]; o1[c] = bb;
        }
        red0[t]  = c0.x + c0.y + c0.z + c0.w;
        red1[t]  = c1.x + c1.y + c1.z + c1.w;
        redd0[t] = diags0[t] + diags0[t+16] + diags0[t+32] + diags0[t+48];
        redd1[t] = diags1[t] + diags1[t+16] + diags1[t+32] + diags1[t+48];
    }
    __syncthreads();
    if (t == 0) {
        float a0=0, a1=0, d0=0, d1=0;
        #pragma unroll
        for (int k = 0; k < 16; k++) { a0 += red0[k]; a1 += red1[k]; d0 += redd0[k]; d1 += redd1[k]; }
        g_ma[n*D_ + 2*dp    ] = a0 * (1.f/MM_);
        g_ma[n*D_ + 2*dp + 1] = a1 * (1.f/MM_);
        g_md[n*D_ + 2*dp    ] = d0 * (1.f/M_);
        g_md[n*D_ + 2*dp + 1] = d1 * (1.f/M_);
    }
}

// ---------------- kernel 2: P[n,s,v] and Q[n,s] ----------------
__global__ __launch_bounds__(128) void pq_kernel(const float* __restrict__ bias) {
    int n   = blockIdx.y;
    int s0  = blockIdx.x * 8;
    int tid = threadIdx.x;
    int v   = tid & 63;
    int h   = tid >> 6;

    __shared__ float2 c13s[D_][8];
    __shared__ float  psum[64][8];
    __shared__ float  qred[8][8];
    const float2* c13g = (const float2*)g_c13;
    for (int idx = tid; idx < D_ * 8; idx += 128) {
        int d = idx >> 3, t = idx & 7;
        c13s[d][t] = c13g[d*S_ + s0 + t];
    }
    __syncthreads();

    const float2* mcdg = (const float2*)g_mcdg;
    float acc[8] = {0.f,0.f,0.f,0.f,0.f,0.f,0.f,0.f};
    int base = (n*D_ + h*64)*M_ + v;
    #pragma unroll 8
    for (int dd = 0; dd < 64; dd++) {
        float2 m = mcdg[base + dd*M_];
        int d = h*64 + dd;
        #pragma unroll
        for (int t = 0; t < 8; t++) {
            float2 c = c13s[d][t];
            acc[t] += c.x * m.x + c.y * m.y;
        }
    }
    if (h == 1) {
        #pragma unroll
        for (int t = 0; t < 8; t++) psum[v][t] = acc[t];
    }
    __syncthreads();
    if (h == 0) {
        #pragma unroll
        for (int t = 0; t < 8; t++)
            g_P[(n*S_ + s0 + t)*M_ + v] = acc[t] + psum[v][t];
    } else {
        int sq = v >> 3, grp = v & 7;
        const float2* c45g = (const float2*)g_c45;
        float qacc = 0.f;
        int d0 = grp * 16;
        #pragma unroll
        for (int dd = 0; dd < 16; dd++) {
            int d = d0 + dd;
            float2 c = c45g[d*S_ + s0 + sq];
            qacc += c.x * g_md[n*D_ + d] + c.y * g_ma[n*D_ + d];
        }
        qred[sq][grp] = qacc;
    }
    __syncthreads();
    if (tid < 8) {
        float qv = 0.f;
        #pragma unroll
        for (int k = 0; k < 8; k++) qv += qred[tid][k];
        g_Q[n*S_ + s0 + tid] = qv + bias[s0 + tid];
    }
}

// ---------------- kernel 3: persistent FP16 GEMM, 4 tiles per CTA -----------------
// Grid (8, 32): CTA (bxg, n) processes bx = bxg*4 .. bxg*4+3 (single wave, 256 CTAs).
// Double-buffered whole-tile B (32KB each) + separate epilogue stage. Tile t+1's
// cp.async issued BEFORE waiting on tile t -> DRAM latency hidden under compute.
#define LDB 136
#define TILE_W (8*8*LDB)               // uint32 words per B tile buffer (8704)
#define EPI_W  (32*LDB)                // epilogue staging words (4352)
#define SMEM_B_TC ((2*TILE_W + EPI_W) * 4)   // 87040 bytes

__global__ __launch_bounds__(256, 2) void gemm_f16_kernel(float* __restrict__ out) {
    extern __shared__ uint32_t smem[];
    uint32_t* Bbuf[2] = { smem, smem + TILE_W };
    float*    epi     = (float*)(smem + 2*TILE_W);

    int n   = blockIdx.y;
    int bxg = blockIdx.x;              // 0..7
    int tid = threadIdx.x;
    int w    = tid >> 5, lane = tid & 31;
    int g    = lane >> 2, tig = lane & 3;
    int wr   = w & 3;                  // s0  = wr*32
    int wc   = w >> 2;                 // ij0 = wc*64

    int dp  = tid >> 5;                // 0..7 (row within chunk)
    int seg = tid & 31;                // 0..31 (16B segment)
    const uint32_t* nbase = g_xh + (size_t)(n * 64) * 4096 + dp * 4096 + seg * 4;

    // prologue: prefetch tile 0
    {
        const uint32_t* src = nbase + (bxg * 4) * 128;
        #pragma unroll
        for (int st = 0; st < 8; st++)
            cp16(&Bbuf[0][(st*8 + dp)*LDB + seg*4], src + (size_t)st * 8 * 4096);
    }
    CP_COMMIT();

    const uint4* af = g_cfrag + wr * 64 + lane * 2;

    #pragma unroll 1
    for (int tt = 0; tt < 4; tt++) {
        int bx = bxg * 4 + tt;
        uint32_t* Bc = Bbuf[tt & 1];
        uint32_t* Bn = Bbuf[(tt & 1) ^ 1];

        // issue next tile's prefetch BEFORE waiting on this tile
        if (tt < 3) {
            const uint32_t* src = nbase + (bx + 1) * 128;
            #pragma unroll
            for (int st = 0; st < 8; st++)
                cp16(&Bn[(st*8 + dp)*LDB + seg*4], src + (size_t)st * 8 * 4096);
        }
        CP_COMMIT();                   // empty group at tt=3 keeps count uniform
        CP_WAIT(1);                    // tile tt resident (≤1 pending = tile tt+1)
        __syncthreads();

        float acc[2][8][4];
        #pragma unroll
        for (int mt = 0; mt < 2; mt++)
            #pragma unroll
            for (int nt = 0; nt < 8; nt++)
                #pragma unroll
                for (int v = 0; v < 4; v++) acc[mt][nt][v] = 0.f;

        int col = wc * 64 + g;
        #pragma unroll
        for (int kc = 0; kc < 8; kc++) {
            const uint32_t* B = Bc + kc * 8 * LDB;
            uint4 a0 = af[kc * 256];
            uint4 a1 = af[kc * 256 + 1];
            uint32_t b[8][2];
            #pragma unroll
            for (int nt = 0; nt < 8; nt++) {
                b[nt][0] = B[(tig    )*LDB + col + nt * 8];
                b[nt][1] = B[(tig + 4)*LDB + col + nt * 8];
            }
            #pragma unroll
            for (int nt = 0; nt < 8; nt++) {
                asm volatile(
                    "mma.sync.aligned.m16n8k16.row.col.f32.f16.f16.f32 "
                    "{%0,%1,%2,%3}, {%4,%5,%6,%7}, {%8,%9}, {%0,%1,%2,%3};"
                    : "+f"(acc[0][nt][0]), "+f"(acc[0][nt][1]),
                      "+f"(acc[0][nt][2]), "+f"(acc[0][nt][3])
                    : "r"(a0.x), "r"(a0.y), "r"(a0.z), "r"(a0.w),
                      "r"(b[nt][0]), "r"(b[nt][1]));
                asm volatile(
                    "mma.sync.aligned.m16n8k16.row.col.f32.f16.f16.f32 "
                    "{%0,%1,%2,%3}, {%4,%5,%6,%7}, {%8,%9}, {%0,%1,%2,%3};"
                    : "+f"(acc[1][nt][0]), "+f"(acc[1][nt][1]),
                      "+f"(acc[1][nt][2]), "+f"(acc[1][nt][3])
                    : "r"(a1.x), "r"(a1.y), "r"(a1.z), "r"(a1.w),
                      "r"(b[nt][0]), "r"(b[nt][1]));
            }
        }

        // epilogue: smem-staged transpose, coalesced stores (next tile's cp.async
        // is in flight underneath this)
        #pragma unroll
        for (int rd = 0; rd < 4; rd++) {
            int mt = rd >> 1, half = rd & 1;
            __syncthreads();
            int sbase = (wr*8 + g)*LDB + wc*64 + tig*2;
            #pragma unroll
            for (int nt = 0; nt < 8; nt++) {
                float2 v;
                v.x = acc[mt][nt][half*2 + 0];
                v.y = acc[mt][nt][half*2 + 1];
                *(float2*)&epi[sbase + nt*8] = v;
            }
            __syncthreads();
            #pragma unroll
            for (int p = 0; p < 4; p++) {
                int row  = w*4 + (lane >> 3);           // 0..31
                int col2 = p*32 + (lane & 7)*4;         // 0..127
                float4 v = *(const float4*)&epi[row*LDB + col2];
                int s     = (row >> 3)*32 + mt*16 + half*8 + (row & 7);
                int i_loc = p >> 1;
                int j     = (p & 1)*32 + (lane & 7)*4;
                const float* Pn = &g_P[(n*S_ + s) * M_];
                float pi = Pn[bx*2 + i_loc] + g_Q[n*S_ + s];
                float4 pj = *(const float4*)&Pn[j];
                float4 r;
                r.x = v.x + pi + pj.x;
                r.y = v.y + pi + pj.y;
                r.z = v.z + pi + pj.z;
                r.w = v.w + pi + pj.w;
                *(float4*)&out[(size_t)(n*S_ + s) * MM_ + (size_t)(bx*2 + i_loc) * M_ + j] = r;
            }
        }
        __syncthreads();               // epi reads done before next tile reuses smem
    }
}

// ---------------- launch ----------------
extern "C" void kernel_launch(void* const* d_in, const int* in_sizes, int n_in,
                              void* d_out, int out_size) {
    const float* x      = (const float*)d_in[0];   // [N,D,M,M]
    const float* coeffs = (const float*)d_in[1];   // [D,S,5]
    const float* bias   = (const float*)d_in[2];   // [1,S,1,1]
    float* out = (float*)d_out;                    // [N,S,M,M]

    static int smem_set = 0;
    if (!smem_set) {
        cudaFuncSetAttribute(gemm_f16_kernel,
                             cudaFuncAttributeMaxDynamicSharedMemorySize, SMEM_B_TC);
        smem_set = 1;
    }

    prep_kernel<<<72, 256>>>(coeffs);
    stats_kernel<<<N_ * 64, 256>>>(x);
    pq_kernel<<<dim3(S_ / 8, N_), 128>>>(bias);
    gemm_f16_kernel<<<dim3(8, N_), 256, SMEM_B_TC>>>(out);
}

// round 17
// speedup vs baseline: 1.0588x; 1.0588x over previous
#include <cuda_runtime.h>
#include <cuda_fp16.h>
#include <cstdint>

// Problem constants
#define N_ 32
#define D_ 128
#define S_ 128
#define M_ 64
#define MM_ (M_*M_)

// ---------------- scratch (__device__ globals; no allocations allowed) ----------------
__device__ uint32_t g_xh[N_*64*4096];   // x as fp16 k-pair packed: [n][dp=d/2][ij]
__device__ uint4    g_cfrag[2048];      // c2 fp16 in m16n8k16 A-fragment order
__device__ float    g_mcdg[N_*D_*M_*2]; // interleaved (mc, dg)
__device__ float    g_md[N_*D_];
__device__ float    g_ma[N_*D_];
__device__ float    g_c13[D_*S_*2];
__device__ float    g_c45[D_*S_*2];
__device__ float    g_P[N_*S_*M_];
__device__ float    g_Q[N_*S_];

__device__ __forceinline__ uint32_t packh2(float lo, float hi) {
    __half2 h = __halves2half2(__float2half_rn(lo), __float2half_rn(hi));
    return *reinterpret_cast<uint32_t*>(&h);
}
__device__ __forceinline__ void cp16(void* s, const void* g) {
    uint32_t sa = (uint32_t)__cvta_generic_to_shared(s);
    asm volatile("cp.async.cg.shared.global [%0], [%1], 16;\n" :: "r"(sa), "l"(g));
}
#define CP_COMMIT() asm volatile("cp.async.commit_group;\n" ::: "memory")
#define CP_WAIT(Nn) asm volatile("cp.async.wait_group %0;\n" :: "n"(Nn) : "memory")

// ---------------- kernel 1: stats + fp16 pack + coeff prep (extra blocks) ----------
__global__ __launch_bounds__(256) void stats_kernel(const float* __restrict__ x,
                                                    const float* __restrict__ coeffs) {
    if (blockIdx.x >= N_*64) {
        int pb = blockIdx.x - N_*64;
        int t  = threadIdx.x;
        if (pb < 64) {
            int idx = pb * 256 + t;            // d*S + s
            const float* c = coeffs + idx * 5;
            g_c13[idx*2]     = 0.5f * c[0];
            g_c13[idx*2 + 1] = 0.5f * c[2];
            g_c45[idx*2]     = c[3];
            g_c45[idx*2 + 1] = c[4];
        } else {
            int fid  = (pb - 64) * 256 + t;    // 0..2047
            int mt   = fid & 1;
            int lane = (fid >> 1) & 31;
            int wr   = (fid >> 6) & 3;
            int kc   = fid >> 8;
            int g    = lane >> 2, tig = lane & 3;
            int srow = wr * 32 + mt * 16 + g;
            int k0   = kc * 16;
            #define C2V(d, s) coeffs[(((d) * S_) + (s)) * 5 + 1]
            uint4 v;
            v.x = packh2(C2V(k0 + 2*tig,     srow    ), C2V(k0 + 2*tig + 1,     srow    ));
            v.y = packh2(C2V(k0 + 2*tig,     srow + 8), C2V(k0 + 2*tig + 1,     srow + 8));
            v.z = packh2(C2V(k0 + 8 + 2*tig, srow    ), C2V(k0 + 8 + 2*tig + 1, srow    ));
            v.w = packh2(C2V(k0 + 8 + 2*tig, srow + 8), C2V(k0 + 8 + 2*tig + 1, srow + 8));
            #undef C2V
            g_cfrag[fid] = v;
        }
        return;
    }

    int blk = blockIdx.x;
    int n   = blk >> 6;
    int dp  = blk & 63;
    const float* p0 = x + ((size_t)(n * D_ + 2*dp)) * MM_;
    const float* p1 = p0 + MM_;
    uint32_t* xo = g_xh + ((size_t)(n * 64 + dp)) * 4096;

    int t = threadIdx.x;
    int q = t & 15, r = t >> 4;

    float4 s0 = make_float4(0,0,0,0), s1 = make_float4(0,0,0,0);
    #pragma unroll
    for (int k = 0; k < 4; k++) {
        int off = (k*16 + r) * M_ + q * 4;
        float4 v0 = *(const float4*)(p0 + off);
        float4 v1 = *(const float4*)(p1 + off);
        s0.x += v0.x; s0.y += v0.y; s0.z += v0.z; s0.w += v0.w;
        s1.x += v1.x; s1.y += v1.y; s1.z += v1.z; s1.w += v1.w;
        uint4 pk;
        pk.x = packh2(v0.x, v1.x);
        pk.y = packh2(v0.y, v1.y);
        pk.z = packh2(v0.z, v1.z);
        pk.w = packh2(v0.w, v1.w);
        *(uint4*)(xo + off) = pk;
    }

    __shared__ float4 part0[256], part1[256];
    __shared__ float  diags0[64], diags1[64];
    __shared__ float  red0[16], red1[16], redd0[16], redd1[16];
    part0[t] = s0; part1[t] = s1;
    if (t < M_) { diags0[t] = p0[t * 65]; diags1[t] = p1[t * 65]; }
    __syncthreads();

    if (t < 16) {
        float4 c0 = part0[t], c1 = part1[t];
        #pragma unroll
        for (int rr = 1; rr < 16; rr++) {
            float4 a = part0[rr*16 + t], b = part1[rr*16 + t];
            c0.x += a.x; c0.y += a.y; c0.z += a.z; c0.w += a.w;
            c1.x += b.x; c1.y += b.y; c1.z += b.z; c1.w += b.w;
        }
        float m0[4] = { c0.x*(1.f/M_), c0.y*(1.f/M_), c0.z*(1.f/M_), c0.w*(1.f/M_) };
        float m1[4] = { c1.x*(1.f/M_), c1.y*(1.f/M_), c1.z*(1.f/M_), c1.w*(1.f/M_) };
        float2* o0 = ((float2*)g_mcdg) + (n*D_ + 2*dp    ) * M_ + t*4;
        float2* o1 = ((float2*)g_mcdg) + (n*D_ + 2*dp + 1) * M_ + t*4;
        #pragma unroll
        for (int c = 0; c < 4; c++) {
            int v = t*4 + c;
            float2 a; a.x = m0[c]; a.y = diags0[v]; o0[c] = a;
            float2 bb; bb.x = m1[c]; bb.y = diags1[v]; o1[c] = bb;
        }
        red0[t]  = c0.x + c0.y + c0.z + c0.w;
        red1[t]  = c1.x + c1.y + c1.z + c1.w;
        redd0[t] = diags0[t] + diags0[t+16] + diags0[t+32] + diags0[t+48];
        redd1[t] = diags1[t] + diags1[t+16] + diags1[t+32] + diags1[t+48];
    }
    __syncthreads();
    if (t == 0) {
        float a0=0, a1=0, d0=0, d1=0;
        #pragma unroll
        for (int k = 0; k < 16; k++) { a0 += red0[k]; a1 += red1[k]; d0 += redd0[k]; d1 += redd1[k]; }
        g_ma[n*D_ + 2*dp    ] = a0 * (1.f/MM_);
        g_ma[n*D_ + 2*dp + 1] = a1 * (1.f/MM_);
        g_md[n*D_ + 2*dp    ] = d0 * (1.f/M_);
        g_md[n*D_ + 2*dp + 1] = d1 * (1.f/M_);
    }
}

// ---------------- kernel 2: P[n,s,v] and Q[n,s] ----------------
__global__ __launch_bounds__(128) void pq_kernel(const float* __restrict__ bias) {
    int n   = blockIdx.y;
    int s0  = blockIdx.x * 8;
    int tid = threadIdx.x;
    int v   = tid & 63;
    int h   = tid >> 6;

    __shared__ float2 c13s[D_][8];
    __shared__ float  psum[64][8];
    __shared__ float  qred[8][8];
    const float2* c13g = (const float2*)g_c13;
    for (int idx = tid; idx < D_ * 8; idx += 128) {
        int d = idx >> 3, t = idx & 7;
        c13s[d][t] = c13g[d*S_ + s0 + t];
    }
    __syncthreads();

    const float2* mcdg = (const float2*)g_mcdg;
    float acc[8] = {0.f,0.f,0.f,0.f,0.f,0.f,0.f,0.f};
    int base = (n*D_ + h*64)*M_ + v;
    #pragma unroll 8
    for (int dd = 0; dd < 64; dd++) {
        float2 m = mcdg[base + dd*M_];
        int d = h*64 + dd;
        #pragma unroll
        for (int t = 0; t < 8; t++) {
            float2 c = c13s[d][t];
            acc[t] += c.x * m.x + c.y * m.y;
        }
    }
    if (h == 1) {
        #pragma unroll
        for (int t = 0; t < 8; t++) psum[v][t] = acc[t];
    }
    __syncthreads();
    if (h == 0) {
        #pragma unroll
        for (int t = 0; t < 8; t++)
            g_P[(n*S_ + s0 + t)*M_ + v] = acc[t] + psum[v][t];
    } else {
        int sq = v >> 3, grp = v & 7;
        const float2* c45g = (const float2*)g_c45;
        float qacc = 0.f;
        int d0 = grp * 16;
        #pragma unroll
        for (int dd = 0; dd < 16; dd++) {
            int d = d0 + dd;
            float2 c = c45g[d*S_ + s0 + sq];
            qacc += c.x * g_md[n*D_ + d] + c.y * g_ma[n*D_ + d];
        }
        qred[sq][grp] = qacc;
    }
    __syncthreads();
    if (tid < 8) {
        float qv = 0.f;
        #pragma unroll
        for (int k = 0; k < 8; k++) qv += qred[tid][k];
        g_Q[n*S_ + s0 + tid] = qv + bias[s0 + tid];
    }
}

// ---------------- kernel 3: FP16 GEMM, 512 threads, 32x32 warp tile ----------------
// CTA tile 128s x 128ij, 16 warps, warp (wr = w&3, wc = w>>2): s = wr*32.., ij = wc*32..
// Whole B tile resident (barrier-free K loop, as R12). Accum 32 regs/thread ->
// __launch_bounds__(512,2) -> 32 warps/SM (50% occ). A-frags per-kc LDG (L1-resident).
#define LDB 136

__global__ __launch_bounds__(512, 2) void gemm_f16_kernel(float* __restrict__ out) {
    __shared__ uint32_t Bs[8][8][LDB];   // 34816 B; epilogue reuses 17408 B

    int n   = blockIdx.y;
    int bx  = blockIdx.x;
    int tid = threadIdx.x;
    int w    = tid >> 5, lane = tid & 31;
    int g    = lane >> 2, tig = lane & 3;
    int wr   = w & 3;                  // s0  = wr*32
    int wc   = w >> 2;                 // ij0 = wc*32 (0..3)

    // loader: 2048 cp16 per tile -> 4 per thread
    const uint32_t* nb = g_xh + (size_t)(n * 64) * 4096 + bx * 128;
    #pragma unroll
    for (int k = 0; k < 4; k++) {
        int idx = tid + k * 512;           // 0..2047
        int st  = idx >> 8;                // chunk
        int f4  = idx & 255;
        int dp  = f4 >> 5, seg = f4 & 31;
        cp16(&Bs[st][dp][seg * 4], nb + (size_t)(st * 8 + dp) * 4096 + seg * 4);
    }
    CP_COMMIT();

    float acc[2][4][4];
    #pragma unroll
    for (int mt = 0; mt < 2; mt++)
        #pragma unroll
        for (int nt = 0; nt < 4; nt++)
            #pragma unroll
            for (int v = 0; v < 4; v++) acc[mt][nt][v] = 0.f;

    const uint4* af = g_cfrag + wr * 64 + lane * 2;

    CP_WAIT(0);
    __syncthreads();                   // the ONLY mainloop barrier

    int col = wc * 32 + g;
    #pragma unroll
    for (int kc = 0; kc < 8; kc++) {
        const uint32_t (*B)[LDB] = Bs[kc];
        uint4 a0 = af[kc * 256];
        uint4 a1 = af[kc * 256 + 1];
        uint32_t b[4][2];
        #pragma unroll
        for (int nt = 0; nt < 4; nt++) {
            b[nt][0] = B[tig    ][col + nt * 8];
            b[nt][1] = B[tig + 4][col + nt * 8];
        }
        #pragma unroll
        for (int nt = 0; nt < 4; nt++) {
            asm volatile(
                "mma.sync.aligned.m16n8k16.row.col.f32.f16.f16.f32 "
                "{%0,%1,%2,%3}, {%4,%5,%6,%7}, {%8,%9}, {%0,%1,%2,%3};"
                : "+f"(acc[0][nt][0]), "+f"(acc[0][nt][1]),
                  "+f"(acc[0][nt][2]), "+f"(acc[0][nt][3])
                : "r"(a0.x), "r"(a0.y), "r"(a0.z), "r"(a0.w),
                  "r"(b[nt][0]), "r"(b[nt][1]));
            asm volatile(
                "mma.sync.aligned.m16n8k16.row.col.f32.f16.f16.f32 "
                "{%0,%1,%2,%3}, {%4,%5,%6,%7}, {%8,%9}, {%0,%1,%2,%3};"
                : "+f"(acc[1][nt][0]), "+f"(acc[1][nt][1]),
                  "+f"(acc[1][nt][2]), "+f"(acc[1][nt][3])
                : "r"(a1.x), "r"(a1.y), "r"(a1.z), "r"(a1.w),
                  "r"(b[nt][0]), "r"(b[nt][1]));
        }
    }

    // ---- epilogue: stage each (mt,half) slice through smem, write coalesced ----
    // STS: 16-lane phase -> 16 distinct even-bank float2 = all 32 banks.
    // LDS.128: 8-lane phase = one row, 8 x 4-bank spans = all 32 banks.
    float* epi = (float*)Bs;           // needs 32*136 = 4352 words

    #pragma unroll
    for (int rd = 0; rd < 4; rd++) {
        int mt = rd >> 1, half = rd & 1;
        __syncthreads();               // previous round's reads (or mainloop) done
        int sbase = (wr*8 + g)*LDB + wc*32 + tig*2;
        #pragma unroll
        for (int nt = 0; nt < 4; nt++) {
            float2 v;
            v.x = acc[mt][nt][half*2 + 0];
            v.y = acc[mt][nt][half*2 + 1];
            *(float2*)&epi[sbase + nt*8] = v;
        }
        __syncthreads();
        {
            int row = w*2 + (lane >> 4);           // 0..31 (s' index)
            int jj  = (lane & 15) * 4;             // 0..60
            int s   = (row >> 3)*32 + mt*16 + half*8 + (row & 7);
            const float* Pn = &g_P[(n*S_ + s) * M_];
            float qn = g_Q[n*S_ + s];
            float4 pj = *(const float4*)&Pn[jj];
            #pragma unroll
            for (int p = 0; p < 2; p++) {          // p = i_loc
                float4 v = *(const float4*)&epi[row*LDB + p*64 + jj];
                float pi = Pn[bx*2 + p] + qn;
                float4 r;
                r.x = v.x + pi + pj.x;
                r.y = v.y + pi + pj.y;
                r.z = v.z + pi + pj.z;
                r.w = v.w + pi + pj.w;
                *(float4*)&out[(size_t)(n*S_ + s) * MM_ + (size_t)(bx*2 + p) * M_ + jj] = r;
            }
        }
    }
}

// ---------------- launch ----------------
extern "C" void kernel_launch(void* const* d_in, const int* in_sizes, int n_in,
                              void* d_out, int out_size) {
    const float* x      = (const float*)d_in[0];   // [N,D,M,M]
    const float* coeffs = (const float*)d_in[1];   // [D,S,5]
    const float* bias   = (const float*)d_in[2];   // [1,S,1,1]
    float* out = (float*)d_out;                    // [N,S,M,M]

    stats_kernel<<<N_ * 64 + 72, 256>>>(x, coeffs);   // stats + pack + coeff prep
    pq_kernel<<<dim3(S_ / 8, N_), 128>>>(bias);
    gemm_f16_kernel<<<dim3(32, N_), 512>>>(out);
}